// round 2
// baseline (speedup 1.0000x reference)
#include <cuda_runtime.h>
#include <cuda_bf16.h>
#include <math.h>

// ----- problem constants (fixed shapes) -----
#define NN     10000
#define EE     30000
#define IN_DIM 1024
#define H1     4
#define C1     512
#define D1     2048          // H1*C1
#define H2     8
#define C2     460
#define D2     3680          // H2*C2
#define E2TOT  40000         // EE + NN (self loops)

// ----- scratch (device globals; no allocations allowed) -----
__device__ float g_q [NN * D1];
__device__ float g_k [NN * D1];
__device__ float g_v [NN * D1];
__device__ float g_h [NN * D1];   // skip GEMM output, then += agg, then elu in place
__device__ float g_gl[NN * D2];
__device__ float g_gr[NN * D2];
__device__ float g_ex1 [EE * H1];
__device__ float g_den1[NN * H1];
__device__ float g_ex2 [E2TOT * H2];
__device__ float g_den2[NN * H2];
__device__ int   g_src[EE];
__device__ int   g_dst[EE];

// =====================================================================
// edge_index ingestion: dtype-agnostic (int64 vs int32), writes int arrays.
// Every thread makes the same deterministic dtype decision from 16 samples.
// =====================================================================
__global__ __launch_bounds__(256)
void cvt_edges(const void* __restrict__ ei_raw)
{
    const long long* e64 = (const long long*)ei_raw;
    const int*       e32 = (const int*)ei_raw;

    // decide dtype: if the buffer really holds int64 pairs, every int64 word
    // is a valid index in [0, NN). If it holds int32, an int64 read combines
    // two indices -> almost surely out of range.
    bool is64 = true;
#pragma unroll
    for (int j = 0; j < 16; j++) {
        long long v = e64[j * 1000];   // < 30000 int64 slots in either layout
        if (v < 0 || v >= NN) { is64 = false; break; }
    }

    int e = blockIdx.x * blockDim.x + threadIdx.x;
    if (e >= EE) return;
    long long s, d;
    if (is64) { s = e64[2 * e];     d = e64[2 * e + 1]; }
    else      { s = e32[2 * e];     d = e32[2 * e + 1]; }
    // clamp defensively: wrong guess => finite wrong answer, not a fault
    if (s < 0) s = 0; if (s >= NN) s = NN - 1;
    if (d < 0) d = 0; if (d >= NN) d = NN - 1;
    g_src[e] = (int)s;
    g_dst[e] = (int)d;
}

// =====================================================================
// SGEMM: C[M,N] = A[M,K] @ B[K,N] + bias[N]
// 128x128 block tile, BK=8, 256 threads, 8x8 per thread, float4 loads.
// Requires K % 8 == 0 and N % 4 == 0 (true for all 6 GEMMs here).
// =====================================================================
#define BM 128
#define BN 128
#define BK 8
#define TM 8
#define TN 8

__global__ __launch_bounds__(256, 2)
void sgemm_bias(const float* __restrict__ A, const float* __restrict__ B,
                const float* __restrict__ bias, float* __restrict__ C,
                int M, int N, int K)
{
    __shared__ float As[BK][BM + 4];
    __shared__ float Bs[BK][BN];

    const int tid  = threadIdx.x;
    const int tx   = tid & 15;        // 0..15 -> N direction
    const int ty   = tid >> 4;        // 0..15 -> M direction
    const int row0 = blockIdx.y * BM;
    const int col0 = blockIdx.x * BN;

    const int aRow = tid >> 1;            // 0..127
    const int aCol = (tid & 1) * 4;       // 0 or 4
    const int bRow = tid >> 5;            // 0..7
    const int bCol = (tid & 31) * 4;      // 0..124

    float acc[TM][TN];
#pragma unroll
    for (int i = 0; i < TM; i++)
#pragma unroll
        for (int j = 0; j < TN; j++) acc[i][j] = 0.f;

    float ra[TM], rb[TN];

    for (int k0 = 0; k0 < K; k0 += BK) {
        float4 av = make_float4(0.f, 0.f, 0.f, 0.f);
        int gr = row0 + aRow;
        if (gr < M)
            av = *(const float4*)&A[(size_t)gr * K + k0 + aCol];
        As[aCol + 0][aRow] = av.x;
        As[aCol + 1][aRow] = av.y;
        As[aCol + 2][aRow] = av.z;
        As[aCol + 3][aRow] = av.w;

        float4 bv = make_float4(0.f, 0.f, 0.f, 0.f);
        int gc = col0 + bCol;
        if (gc + 3 < N)
            bv = *(const float4*)&B[(size_t)(k0 + bRow) * N + gc];
        *(float4*)&Bs[bRow][bCol] = bv;

        __syncthreads();

#pragma unroll
        for (int kk = 0; kk < BK; kk++) {
#pragma unroll
            for (int i = 0; i < TM; i++) ra[i] = As[kk][ty * TM + i];
#pragma unroll
            for (int j = 0; j < TN; j++) rb[j] = Bs[kk][tx * TN + j];
#pragma unroll
            for (int i = 0; i < TM; i++)
#pragma unroll
                for (int j = 0; j < TN; j++)
                    acc[i][j] = fmaf(ra[i], rb[j], acc[i][j]);
        }
        __syncthreads();
    }

#pragma unroll
    for (int i = 0; i < TM; i++) {
        int gr = row0 + ty * TM + i;
        if (gr >= M) continue;
#pragma unroll
        for (int j = 0; j < TN; j += 4) {
            int gc = col0 + tx * TN + j;
            if (gc + 3 < N) {
                float4 o;
                o.x = acc[i][j + 0] + bias[gc + 0];
                o.y = acc[i][j + 1] + bias[gc + 1];
                o.z = acc[i][j + 2] + bias[gc + 2];
                o.w = acc[i][j + 3] + bias[gc + 3];
                *(float4*)&C[(size_t)gr * N + gc] = o;
            }
        }
    }
}

// =====================================================================
// zero the softmax denominators
// =====================================================================
__global__ void zero_denoms()
{
    int i = blockIdx.x * blockDim.x + threadIdx.x;
    if (i < NN * H1) g_den1[i] = 0.f;
    if (i < NN * H2) g_den2[i] = 0.f;
}

// =====================================================================
// layer-1 edge attention: alpha[e,h] = <q[dst,h,:], k[src,h,:]>/sqrt(C1)
// store exp(alpha); accumulate denom per (dst,h). 1 block / edge, warp / head.
// =====================================================================
__global__ __launch_bounds__(128)
void attn1()
{
    int e    = blockIdx.x;
    int h    = threadIdx.x >> 5;
    int lane = threadIdx.x & 31;
    int s = g_src[e];
    int d = g_dst[e];

    const float4* qp = (const float4*)&g_q[(size_t)d * D1 + h * C1];
    const float4* kp = (const float4*)&g_k[(size_t)s * D1 + h * C1];
    float acc = 0.f;
#pragma unroll 4
    for (int i = lane; i < C1 / 4; i += 32) {
        float4 a = qp[i], b = kp[i];
        acc += a.x * b.x + a.y * b.y + a.z * b.z + a.w * b.w;
    }
#pragma unroll
    for (int o = 16; o; o >>= 1) acc += __shfl_xor_sync(0xFFFFFFFFu, acc, o);
    if (lane == 0) {
        float ex = expf(acc * 0.04419417382415922f);  // / sqrt(512)
        g_ex1[e * H1 + h] = ex;
        atomicAdd(&g_den1[d * H1 + h], ex);
    }
}

// =====================================================================
// layer-1 aggregate: h[dst] += v[src] * softmax_w   (h already holds skip GEMM)
// =====================================================================
__global__ __launch_bounds__(256)
void agg1()
{
    int e = blockIdx.x;
    int s = g_src[e];
    int d = g_dst[e];
    for (int c = threadIdx.x * 4; c < D1; c += 256 * 4) {
        int h = c >> 9;  // c / C1
        float w = g_ex1[e * H1 + h] / (g_den1[d * H1 + h] + 1e-16f);
        float4 vv = *(const float4*)&g_v[(size_t)s * D1 + c];
        float* hp = &g_h[(size_t)d * D1 + c];
        atomicAdd(hp + 0, vv.x * w);
        atomicAdd(hp + 1, vv.y * w);
        atomicAdd(hp + 2, vv.z * w);
        atomicAdd(hp + 3, vv.w * w);
    }
}

// =====================================================================
// ELU in place on g_h
// =====================================================================
__global__ void elu_inplace()
{
    int i = blockIdx.x * blockDim.x + threadIdx.x;
    if (i < NN * D1) {
        float x = g_h[i];
        g_h[i] = (x > 0.f) ? x : expm1f(x);
    }
}

// =====================================================================
// layer-2 edge attention over E2 = E + N edges (self loops appended)
// a[e,h] = sum_c leaky_relu(gl[s,h,c]+gr[d,h,c], 0.2) * att[h,c]
// =====================================================================
__global__ __launch_bounds__(256)
void attn2(const float* __restrict__ att)
{
    int e    = blockIdx.x;
    int h    = threadIdx.x >> 5;
    int lane = threadIdx.x & 31;
    int s, d;
    if (e < EE) { s = g_src[e]; d = g_dst[e]; }
    else        { s = d = e - EE; }

    const float* glp = &g_gl[(size_t)s * D2 + h * C2];
    const float* grp = &g_gr[(size_t)d * D2 + h * C2];
    const float* ap  = &att[h * C2];
    float acc = 0.f;
    for (int i = lane; i < C2; i += 32) {
        float x = glp[i] + grp[i];
        x = (x > 0.f) ? x : 0.2f * x;
        acc += x * ap[i];
    }
#pragma unroll
    for (int o = 16; o; o >>= 1) acc += __shfl_xor_sync(0xFFFFFFFFu, acc, o);
    if (lane == 0) {
        float ex = expf(acc);
        g_ex2[e * H2 + h] = ex;
        atomicAdd(&g_den2[d * H2 + h], ex);
    }
}

// =====================================================================
// init out with b_out
// =====================================================================
__global__ void out_init(float* __restrict__ out, const float* __restrict__ b_out)
{
    int i = blockIdx.x * blockDim.x + threadIdx.x;
    if (i < NN * C2) out[i] = b_out[i % C2];
}

// =====================================================================
// layer-2 aggregate: out[d,c] += (1/H2) * sum_h gl[s,h,c] * w2[e,h]
// =====================================================================
__global__ __launch_bounds__(256)
void agg2(float* __restrict__ out)
{
    int e = blockIdx.x;
    int s, d;
    if (e < EE) { s = g_src[e]; d = g_dst[e]; }
    else        { s = d = e - EE; }

    __shared__ float w[H2];
    if (threadIdx.x < H2)
        w[threadIdx.x] = g_ex2[e * H2 + threadIdx.x] /
                         (g_den2[d * H2 + threadIdx.x] + 1e-16f) * (1.f / H2);
    __syncthreads();

    const float* glp = &g_gl[(size_t)s * D2];
    for (int c = threadIdx.x; c < C2; c += 256) {
        float acc = 0.f;
#pragma unroll
        for (int h = 0; h < H2; h++) acc += glp[h * C2 + c] * w[h];
        atomicAdd(&out[(size_t)d * C2 + c], acc);
    }
}

// =====================================================================
// host launcher
// =====================================================================
extern "C" void kernel_launch(void* const* d_in, const int* in_sizes, int n_in,
                              void* d_out, int out_size)
{
    const float* x     = (const float*)d_in[0];
    const void*  ei    = d_in[1];
    const float* Wq    = (const float*)d_in[2];
    const float* bq    = (const float*)d_in[3];
    const float* Wk    = (const float*)d_in[4];
    const float* bk    = (const float*)d_in[5];
    const float* Wv    = (const float*)d_in[6];
    const float* bv    = (const float*)d_in[7];
    const float* Wskip = (const float*)d_in[8];
    const float* bskip = (const float*)d_in[9];
    const float* Wl    = (const float*)d_in[10];
    const float* bl    = (const float*)d_in[11];
    const float* Wr    = (const float*)d_in[12];
    const float* br    = (const float*)d_in[13];
    const float* att   = (const float*)d_in[14];
    const float* b_out = (const float*)d_in[15];
    float*       out   = (float*)d_out;

    float *pq, *pk, *pv, *ph, *pgl, *pgr;
    cudaGetSymbolAddress((void**)&pq,  g_q);
    cudaGetSymbolAddress((void**)&pk,  g_k);
    cudaGetSymbolAddress((void**)&pv,  g_v);
    cudaGetSymbolAddress((void**)&ph,  g_h);
    cudaGetSymbolAddress((void**)&pgl, g_gl);
    cudaGetSymbolAddress((void**)&pgr, g_gr);

    // edge ingestion + denominator reset (graph replays must reset state)
    cvt_edges<<<(EE + 255) / 256, 256>>>(ei);
    zero_denoms<<<(NN * H2 + 255) / 256, 256>>>();

    // --- layer 1 GEMMs ---
    dim3 g1((D1 + BN - 1) / BN, (NN + BM - 1) / BM);   // 16 x 79
    sgemm_bias<<<g1, 256>>>(x, Wq,    bq,    pq, NN, D1, IN_DIM);
    sgemm_bias<<<g1, 256>>>(x, Wk,    bk,    pk, NN, D1, IN_DIM);
    sgemm_bias<<<g1, 256>>>(x, Wv,    bv,    pv, NN, D1, IN_DIM);
    sgemm_bias<<<g1, 256>>>(x, Wskip, bskip, ph, NN, D1, IN_DIM);  // h starts as skip

    // --- layer 1 attention + aggregation ---
    attn1<<<EE, 128>>>();
    agg1 <<<EE, 256>>>();
    elu_inplace<<<(NN * D1 + 255) / 256, 256>>>();

    // --- layer 2 GEMMs ---
    dim3 g2((D2 + BN - 1) / BN, (NN + BM - 1) / BM);   // 29 x 79
    sgemm_bias<<<g2, 256>>>(ph, Wl, bl, pgl, NN, D2, D1);
    sgemm_bias<<<g2, 256>>>(ph, Wr, br, pgr, NN, D2, D1);

    // --- layer 2 attention + output ---
    attn2<<<E2TOT, 256>>>(att);
    out_init<<<(NN * C2 + 255) / 256, 256>>>(out, b_out);
    agg2<<<E2TOT, 256>>>(out);
}

// round 4
// speedup vs baseline: 2.2958x; 2.2958x over previous
#include <cuda_runtime.h>
#include <cuda_bf16.h>
#include <math.h>
#include <stdint.h>

// ----- problem constants (fixed shapes) -----
#define NN     10000
#define EE     30000
#define IN_DIM 1024
#define H1     4
#define C1     512
#define D1     2048          // H1*C1
#define H2     8
#define C2     460
#define D2     3680          // H2*C2
#define D2PAD  3712          // 29*128
#define E2TOT  40000         // EE + NN (self loops)

// ----- scratch (device globals; no allocations allowed) -----
__device__ float g_q [NN * D1];
__device__ float g_k [NN * D1];
__device__ float g_v [NN * D1];
__device__ float g_h [NN * D1];   // skip GEMM output, then += agg (fp32)
__device__ float g_gl[NN * D2];
__device__ float g_gr[NN * D2];
__device__ float g_ex1 [EE * H1];
__device__ float g_den1[NN * H1];
__device__ float g_ex2 [E2TOT * H2];
__device__ float g_den2[NN * H2];
__device__ int   g_src[EE];
__device__ int   g_dst[EE];

// bf16 split operands
__device__ __nv_bfloat16 g_xhi[NN * IN_DIM];
__device__ __nv_bfloat16 g_xlo[NN * IN_DIM];
__device__ __nv_bfloat16 g_hhi[NN * D1];
__device__ __nv_bfloat16 g_hlo[NN * D1];
// pre-transposed weights, K-major [Npad, K]
__device__ __nv_bfloat16 g_bt1hi[4 * D1 * IN_DIM];
__device__ __nv_bfloat16 g_bt1lo[4 * D1 * IN_DIM];
__device__ __nv_bfloat16 g_bt2hi[2 * D2PAD * D1];
__device__ __nv_bfloat16 g_bt2lo[2 * D2PAD * D1];

// ===================== GEMM (mma.sync bf16x3) =====================
// C[M,N] = (Ahi+Alo)[M,K] @ (Bhi+Blo)^T  (B stored [Npad,K] K-major) + bias.
// Tile 128x128, BK=32 bf16, padded smem stride 80B (conflict-free b32 frags),
// 2-stage cp.async pipeline, warp tile 32m x 64n via m16n8k16 HMMA.
#define SMSTRIDE_B 80                    // bytes per 32-elem row (padded)
#define TILE_B     (128 * SMSTRIDE_B)    // 10240 per operand
#define STAGE_B    (4 * TILE_B)          // 40960
#define GEMM_SMEM  (2 * STAGE_B)         // 81920

__device__ __forceinline__ uint32_t smem_u32(const void* p) {
    uint32_t a;
    asm("{ .reg .u64 t; cvta.to.shared.u64 t, %1; cvt.u32.u64 %0, t; }" : "=r"(a) : "l"(p));
    return a;
}

__device__ __forceinline__ void mma16816(float* c, const uint32_t* a, const uint32_t* b)
{
    asm volatile(
        "mma.sync.aligned.m16n8k16.row.col.f32.bf16.bf16.f32 "
        "{%0,%1,%2,%3}, {%4,%5,%6,%7}, {%8,%9}, {%0,%1,%2,%3};"
        : "+f"(c[0]), "+f"(c[1]), "+f"(c[2]), "+f"(c[3])
        : "r"(a[0]), "r"(a[1]), "r"(a[2]), "r"(a[3]), "r"(b[0]), "r"(b[1]));
}

__global__ __launch_bounds__(256)
void gemm_mma(const __nv_bfloat16* __restrict__ Ahi, const __nv_bfloat16* __restrict__ Alo,
              const __nv_bfloat16* __restrict__ Bhi, const __nv_bfloat16* __restrict__ Blo,
              const float* __restrict__ bias, float* __restrict__ C,
              int M, int N, int K)
{
    extern __shared__ char smem[];
    const uint32_t sb = smem_u32(smem);
    const int tid  = threadIdx.x;
    const int wid  = tid >> 5, lane = tid & 31;
    const int row0 = blockIdx.y * 128;
    const int col0 = blockIdx.x * 128;
    const int KT   = K >> 5;

    // ---- loader mapping: 4 operands x 64 threads; 128 rows x 4 x 16B chunks ----
    const int op     = tid >> 6;          // 0 Ahi, 1 Alo, 2 Bhi, 3 Blo
    const int t64    = tid & 63;
    const int lchunk = t64 & 3;           // 16B chunk in 64B row
    const int lrow0  = t64 >> 2;          // 0..15
    const __nv_bfloat16* lbase = (op == 0) ? Ahi : (op == 1) ? Alo : (op == 2) ? Bhi : Blo;
    const int  lr0 = (op < 2) ? row0 : col0;
    const bool isA = (op < 2);

    auto load_stage = [&](int stage, int kt) {
        uint32_t sdst0 = sb + stage * STAGE_B + op * TILE_B + lchunk * 16;
        const char* gsrc0 = (const char*)lbase + (size_t)kt * 64 + lchunk * 16;
#pragma unroll
        for (int rr = 0; rr < 8; rr++) {
            int r    = lrow0 + rr * 16;
            int grow = lr0 + r;
            int sz   = 16;
            if (isA && grow >= M) { grow = M - 1; sz = 0; }   // zero-fill OOB rows
            const char* src = gsrc0 + (size_t)grow * ((size_t)K * 2);
            uint32_t dst = sdst0 + (uint32_t)r * SMSTRIDE_B;
            asm volatile("cp.async.cg.shared.global [%0], [%1], 16, %2;"
                         :: "r"(dst), "l"(src), "r"(sz));
        }
    };

    // ---- compute mapping ----
    const int wm = wid & 3;               // 4 m-groups of 32 rows
    const int wn = wid >> 2;              // 2 n-groups of 64 cols
    const int g  = lane >> 2;             // 0..7
    const int t  = lane & 3;              // 0..3

    float acc[2][8][4];
#pragma unroll
    for (int i = 0; i < 2; i++)
#pragma unroll
        for (int j = 0; j < 8; j++)
#pragma unroll
            for (int r = 0; r < 4; r++) acc[i][j][r] = 0.f;

    // prologue
    load_stage(0, 0);
    asm volatile("cp.async.commit_group;" ::: "memory");
    load_stage(1, 1);
    asm volatile("cp.async.commit_group;" ::: "memory");

    for (int kt = 0; kt < KT; kt++) {
        asm volatile("cp.async.wait_group 1;" ::: "memory");
        __syncthreads();

        const char* sAh = smem + (kt & 1) * STAGE_B;
        const char* sAl = sAh + TILE_B;
        const char* sBh = sAh + 2 * TILE_B;
        const char* sBl = sAh + 3 * TILE_B;

#pragma unroll
        for (int kh = 0; kh < 2; kh++) {
            const int kb = kh * 32 + t * 4;   // byte offset of col t*2 (+16 for +8 elems)

            uint32_t ah[2][4], al[2][4];
#pragma unroll
            for (int i = 0; i < 2; i++) {
                int ra = wm * 32 + i * 16 + g;
                ah[i][0] = *(const uint32_t*)(sAh + ra * SMSTRIDE_B + kb);
                ah[i][1] = *(const uint32_t*)(sAh + (ra + 8) * SMSTRIDE_B + kb);
                ah[i][2] = *(const uint32_t*)(sAh + ra * SMSTRIDE_B + kb + 16);
                ah[i][3] = *(const uint32_t*)(sAh + (ra + 8) * SMSTRIDE_B + kb + 16);
                al[i][0] = *(const uint32_t*)(sAl + ra * SMSTRIDE_B + kb);
                al[i][1] = *(const uint32_t*)(sAl + (ra + 8) * SMSTRIDE_B + kb);
                al[i][2] = *(const uint32_t*)(sAl + ra * SMSTRIDE_B + kb + 16);
                al[i][3] = *(const uint32_t*)(sAl + (ra + 8) * SMSTRIDE_B + kb + 16);
            }
#pragma unroll
            for (int j = 0; j < 8; j++) {
                int rb = wn * 64 + j * 8 + g;
                uint32_t bh[2], bl[2];
                bh[0] = *(const uint32_t*)(sBh + rb * SMSTRIDE_B + kb);
                bh[1] = *(const uint32_t*)(sBh + rb * SMSTRIDE_B + kb + 16);
                bl[0] = *(const uint32_t*)(sBl + rb * SMSTRIDE_B + kb);
                bl[1] = *(const uint32_t*)(sBl + rb * SMSTRIDE_B + kb + 16);
#pragma unroll
                for (int i = 0; i < 2; i++) {
                    mma16816(acc[i][j], ah[i], bh);
                    mma16816(acc[i][j], ah[i], bl);
                    mma16816(acc[i][j], al[i], bh);
                }
            }
        }

        __syncthreads();
        if (kt + 2 < KT) load_stage(kt & 1, kt + 2);
        asm volatile("cp.async.commit_group;" ::: "memory");
    }

    // ---- epilogue: bias + store ----
#pragma unroll
    for (int i = 0; i < 2; i++) {
        int gr0 = row0 + wm * 32 + i * 16 + g;
#pragma unroll
        for (int j = 0; j < 8; j++) {
            int gc = col0 + wn * 64 + j * 8 + t * 2;
            if (gc < N) {
                float b0 = bias[gc], b1 = bias[gc + 1];
                if (gr0 < M) {
                    float2 o = make_float2(acc[i][j][0] + b0, acc[i][j][1] + b1);
                    *(float2*)&C[(size_t)gr0 * N + gc] = o;
                }
                if (gr0 + 8 < M) {
                    float2 o = make_float2(acc[i][j][2] + b0, acc[i][j][3] + b1);
                    *(float2*)&C[(size_t)(gr0 + 8) * N + gc] = o;
                }
            }
        }
    }
}

// ===================== conversion / transpose prologues =====================
__global__ __launch_bounds__(256)
void split_x(const float* __restrict__ x)
{
    int i = blockIdx.x * blockDim.x + threadIdx.x;
    if (i < NN * IN_DIM) {
        float v = x[i];
        __nv_bfloat16 h = __float2bfloat16(v);
        g_xhi[i] = h;
        g_xlo[i] = __float2bfloat16(v - __bfloat162float(h));
    }
}

__global__ __launch_bounds__(256)
void elu_split()
{
    int i = blockIdx.x * blockDim.x + threadIdx.x;
    if (i < NN * D1) {
        float v = g_h[i];
        v = (v > 0.f) ? v : expm1f(v);
        __nv_bfloat16 h = __float2bfloat16(v);
        g_hhi[i] = h;
        g_hlo[i] = __float2bfloat16(v - __bfloat162float(h));
    }
}

// W[K,N] (n-contig) -> BT[Npad,K] K-major, split hi/lo. grid (K/32, Npad/32), block(32,8)
__global__ __launch_bounds__(256)
void transpose_split(const float* __restrict__ W, __nv_bfloat16* __restrict__ bthi,
                     __nv_bfloat16* __restrict__ btlo, int K, int N)
{
    __shared__ float tbuf[32][33];
    int k0 = blockIdx.x * 32, n0 = blockIdx.y * 32;
    int tx = threadIdx.x, ty = threadIdx.y;
#pragma unroll
    for (int i = ty; i < 32; i += 8) {
        int n = n0 + tx;
        tbuf[i][tx] = (n < N) ? W[(size_t)(k0 + i) * N + n] : 0.f;
    }
    __syncthreads();
#pragma unroll
    for (int i = ty; i < 32; i += 8) {
        float v = tbuf[tx][i];                    // = W[k0+tx][n0+i]
        __nv_bfloat16 h = __float2bfloat16(v);
        size_t o = (size_t)(n0 + i) * K + (k0 + tx);
        bthi[o] = h;
        btlo[o] = __float2bfloat16(v - __bfloat162float(h));
    }
}

// ===================== graph kernels (R2-proven) =====================
__global__ __launch_bounds__(256)
void cvt_edges(const void* __restrict__ ei_raw)
{
    const long long* e64 = (const long long*)ei_raw;
    const int*       e32 = (const int*)ei_raw;
    bool is64 = true;
#pragma unroll
    for (int j = 0; j < 16; j++) {
        long long v = e64[j * 1000];
        if (v < 0 || v >= NN) { is64 = false; break; }
    }
    int e = blockIdx.x * blockDim.x + threadIdx.x;
    if (e >= EE) return;
    long long s, d;
    if (is64) { s = e64[2 * e]; d = e64[2 * e + 1]; }
    else      { s = e32[2 * e]; d = e32[2 * e + 1]; }
    if (s < 0) s = 0; if (s >= NN) s = NN - 1;
    if (d < 0) d = 0; if (d >= NN) d = NN - 1;
    g_src[e] = (int)s;
    g_dst[e] = (int)d;
}

__global__ void zero_denoms()
{
    int i = blockIdx.x * blockDim.x + threadIdx.x;
    if (i < NN * H1) g_den1[i] = 0.f;
    if (i < NN * H2) g_den2[i] = 0.f;
}

__global__ __launch_bounds__(128)
void attn1()
{
    int e = blockIdx.x;
    int h = threadIdx.x >> 5;
    int lane = threadIdx.x & 31;
    int s = g_src[e], d = g_dst[e];
    const float4* qp = (const float4*)&g_q[(size_t)d * D1 + h * C1];
    const float4* kp = (const float4*)&g_k[(size_t)s * D1 + h * C1];
    float acc = 0.f;
#pragma unroll 4
    for (int i = lane; i < C1 / 4; i += 32) {
        float4 a = qp[i], b = kp[i];
        acc += a.x * b.x + a.y * b.y + a.z * b.z + a.w * b.w;
    }
#pragma unroll
    for (int o = 16; o; o >>= 1) acc += __shfl_xor_sync(0xFFFFFFFFu, acc, o);
    if (lane == 0) {
        float ex = expf(acc * 0.04419417382415922f);
        g_ex1[e * H1 + h] = ex;
        atomicAdd(&g_den1[d * H1 + h], ex);
    }
}

__global__ __launch_bounds__(256)
void agg1()
{
    int e = blockIdx.x;
    int s = g_src[e], d = g_dst[e];
    for (int c = threadIdx.x * 4; c < D1; c += 256 * 4) {
        int h = c >> 9;
        float w = g_ex1[e * H1 + h] / (g_den1[d * H1 + h] + 1e-16f);
        float4 vv = *(const float4*)&g_v[(size_t)s * D1 + c];
        float* hp = &g_h[(size_t)d * D1 + c];
        atomicAdd(hp + 0, vv.x * w);
        atomicAdd(hp + 1, vv.y * w);
        atomicAdd(hp + 2, vv.z * w);
        atomicAdd(hp + 3, vv.w * w);
    }
}

__global__ __launch_bounds__(256)
void attn2(const float* __restrict__ att)
{
    int e = blockIdx.x;
    int h = threadIdx.x >> 5;
    int lane = threadIdx.x & 31;
    int s, d;
    if (e < EE) { s = g_src[e]; d = g_dst[e]; }
    else        { s = d = e - EE; }
    const float* glp = &g_gl[(size_t)s * D2 + h * C2];
    const float* grp = &g_gr[(size_t)d * D2 + h * C2];
    const float* ap  = &att[h * C2];
    float acc = 0.f;
    for (int i = lane; i < C2; i += 32) {
        float x = glp[i] + grp[i];
        x = (x > 0.f) ? x : 0.2f * x;
        acc += x * ap[i];
    }
#pragma unroll
    for (int o = 16; o; o >>= 1) acc += __shfl_xor_sync(0xFFFFFFFFu, acc, o);
    if (lane == 0) {
        float ex = expf(acc);
        g_ex2[e * H2 + h] = ex;
        atomicAdd(&g_den2[d * H2 + h], ex);
    }
}

__global__ void out_init(float* __restrict__ out, const float* __restrict__ b_out)
{
    int i = blockIdx.x * blockDim.x + threadIdx.x;
    if (i < NN * C2) out[i] = b_out[i % C2];
}

__global__ __launch_bounds__(256)
void agg2(float* __restrict__ out)
{
    int e = blockIdx.x;
    int s, d;
    if (e < EE) { s = g_src[e]; d = g_dst[e]; }
    else        { s = d = e - EE; }
    __shared__ float w[H2];
    if (threadIdx.x < H2)
        w[threadIdx.x] = g_ex2[e * H2 + threadIdx.x] /
                         (g_den2[d * H2 + threadIdx.x] + 1e-16f) * (1.f / H2);
    __syncthreads();
    const float* glp = &g_gl[(size_t)s * D2];
    for (int c = threadIdx.x; c < C2; c += 256) {
        float acc = 0.f;
#pragma unroll
        for (int h = 0; h < H2; h++) acc += glp[h * C2 + c] * w[h];
        atomicAdd(&out[(size_t)d * C2 + c], acc);
    }
}

// ===================== host launcher =====================
extern "C" void kernel_launch(void* const* d_in, const int* in_sizes, int n_in,
                              void* d_out, int out_size)
{
    const float* x     = (const float*)d_in[0];
    const void*  ei    = d_in[1];
    const float* Wq    = (const float*)d_in[2];
    const float* bq    = (const float*)d_in[3];
    const float* Wk    = (const float*)d_in[4];
    const float* bk    = (const float*)d_in[5];
    const float* Wv    = (const float*)d_in[6];
    const float* bv    = (const float*)d_in[7];
    const float* Wskip = (const float*)d_in[8];
    const float* bskip = (const float*)d_in[9];
    const float* Wl    = (const float*)d_in[10];
    const float* bl    = (const float*)d_in[11];
    const float* Wr    = (const float*)d_in[12];
    const float* br    = (const float*)d_in[13];
    const float* att   = (const float*)d_in[14];
    const float* b_out = (const float*)d_in[15];
    float*       out   = (float*)d_out;

    float *pq, *pk, *pv, *ph, *pgl, *pgr;
    cudaGetSymbolAddress((void**)&pq,  g_q);
    cudaGetSymbolAddress((void**)&pk,  g_k);
    cudaGetSymbolAddress((void**)&pv,  g_v);
    cudaGetSymbolAddress((void**)&ph,  g_h);
    cudaGetSymbolAddress((void**)&pgl, g_gl);
    cudaGetSymbolAddress((void**)&pgr, g_gr);
    __nv_bfloat16 *pxhi, *pxlo, *phhi, *phlo, *pb1h, *pb1l, *pb2h, *pb2l;
    cudaGetSymbolAddress((void**)&pxhi, g_xhi);
    cudaGetSymbolAddress((void**)&pxlo, g_xlo);
    cudaGetSymbolAddress((void**)&phhi, g_hhi);
    cudaGetSymbolAddress((void**)&phlo, g_hlo);
    cudaGetSymbolAddress((void**)&pb1h, g_bt1hi);
    cudaGetSymbolAddress((void**)&pb1l, g_bt1lo);
    cudaGetSymbolAddress((void**)&pb2h, g_bt2hi);
    cudaGetSymbolAddress((void**)&pb2l, g_bt2lo);

    cudaFuncSetAttribute(gemm_mma, cudaFuncAttributeMaxDynamicSharedMemorySize, GEMM_SMEM);

    // edge ingestion + denominator reset (graph replays must reset state)
    cvt_edges<<<(EE + 255) / 256, 256>>>(ei);
    zero_denoms<<<(NN * H2 + 255) / 256, 256>>>();

    // operand conversions
    split_x<<<(NN * IN_DIM + 255) / 256, 256>>>(x);
    {
        dim3 blk(32, 8);
        dim3 t1(IN_DIM / 32, D1 / 32);        // (32, 64)
        size_t w1 = (size_t)D1 * IN_DIM;
        transpose_split<<<t1, blk>>>(Wq,    pb1h + 0 * w1, pb1l + 0 * w1, IN_DIM, D1);
        transpose_split<<<t1, blk>>>(Wk,    pb1h + 1 * w1, pb1l + 1 * w1, IN_DIM, D1);
        transpose_split<<<t1, blk>>>(Wv,    pb1h + 2 * w1, pb1l + 2 * w1, IN_DIM, D1);
        transpose_split<<<t1, blk>>>(Wskip, pb1h + 3 * w1, pb1l + 3 * w1, IN_DIM, D1);
        dim3 t2(D1 / 32, D2PAD / 32);         // (64, 116)
        size_t w2 = (size_t)D2PAD * D1;
        transpose_split<<<t2, blk>>>(Wl, pb2h + 0 * w2, pb2l + 0 * w2, D1, D2);
        transpose_split<<<t2, blk>>>(Wr, pb2h + 1 * w2, pb2l + 1 * w2, D1, D2);
    }

    // --- layer 1 GEMMs (HMMA bf16x3) ---
    {
        dim3 g1(D1 / 128, (NN + 127) / 128);  // (16, 79)
        size_t w1 = (size_t)D1 * IN_DIM;
        gemm_mma<<<g1, 256, GEMM_SMEM>>>(pxhi, pxlo, pb1h + 0 * w1, pb1l + 0 * w1, bq,    pq, NN, D1, IN_DIM);
        gemm_mma<<<g1, 256, GEMM_SMEM>>>(pxhi, pxlo, pb1h + 1 * w1, pb1l + 1 * w1, bk,    pk, NN, D1, IN_DIM);
        gemm_mma<<<g1, 256, GEMM_SMEM>>>(pxhi, pxlo, pb1h + 2 * w1, pb1l + 2 * w1, bv,    pv, NN, D1, IN_DIM);
        gemm_mma<<<g1, 256, GEMM_SMEM>>>(pxhi, pxlo, pb1h + 3 * w1, pb1l + 3 * w1, bskip, ph, NN, D1, IN_DIM);
    }

    // --- layer 1 attention + aggregation ---
    attn1<<<EE, 128>>>();
    agg1 <<<EE, 256>>>();
    elu_split<<<(NN * D1 + 255) / 256, 256>>>();

    // --- layer 2 GEMMs ---
    {
        dim3 g2(D2PAD / 128, (NN + 127) / 128); // (29, 79)
        size_t w2 = (size_t)D2PAD * D1;
        gemm_mma<<<g2, 256, GEMM_SMEM>>>(phhi, phlo, pb2h + 0 * w2, pb2l + 0 * w2, bl, pgl, NN, D2, D1);
        gemm_mma<<<g2, 256, GEMM_SMEM>>>(phhi, phlo, pb2h + 1 * w2, pb2l + 1 * w2, br, pgr, NN, D2, D1);
    }

    // --- layer 2 attention + output ---
    attn2<<<E2TOT, 256>>>(att);
    out_init<<<(NN * C2 + 255) / 256, 256>>>(out, b_out);
    agg2<<<E2TOT, 256>>>(out);
}

// round 5
// speedup vs baseline: 2.3562x; 1.0263x over previous
#include <cuda_runtime.h>
#include <cuda_bf16.h>
#include <math.h>
#include <stdint.h>

// ----- problem constants (fixed shapes) -----
#define NN     10000
#define EE     30000
#define IN_DIM 1024
#define H1     4
#define C1     512
#define D1     2048          // H1*C1
#define H2     8
#define C2     460
#define D2     3680          // H2*C2
#define D2PAD  3712          // 29*128
#define E2TOT  40000         // EE + NN (self loops)

#define S1     8192          // packed L1 output row stride: [q|k|v|skip]
#define OFF_Q  0
#define OFF_K  2048
#define OFF_V  4096
#define OFF_H  6144
#define S2     7424          // packed L2 output row stride: [gl(3712)|gr(3712)]
#define N1TOT  8192
#define N2TOT  7424

// ----- scratch (device globals; no allocations allowed) -----
__device__ float g_b1[NN * S1];       // q|k|v|h packed
__device__ float g_b2[NN * S2];       // gl|gr packed
__device__ float g_ex1 [EE * H1];
__device__ float g_den1[NN * H1];
__device__ float g_ex2 [E2TOT * H2];
__device__ float g_den2[NN * H2];
__device__ int   g_src[EE];
__device__ int   g_dst[EE];
__device__ float g_bias1[N1TOT];
__device__ float g_bias2[N2TOT];

// bf16 split operands
__device__ __nv_bfloat16 g_xhi[NN * IN_DIM];
__device__ __nv_bfloat16 g_xlo[NN * IN_DIM];
__device__ __nv_bfloat16 g_hhi[NN * D1];
__device__ __nv_bfloat16 g_hlo[NN * D1];
// pre-transposed weights, K-major [Ntot, K] (L1: 4 slots contig = 8192 rows)
__device__ __nv_bfloat16 g_bt1hi[4 * D1 * IN_DIM];
__device__ __nv_bfloat16 g_bt1lo[4 * D1 * IN_DIM];
__device__ __nv_bfloat16 g_bt2hi[2 * D2PAD * D1];
__device__ __nv_bfloat16 g_bt2lo[2 * D2PAD * D1];

// ===================== GEMM (mma.sync bf16x3, ldmatrix, 3-stage) ===========
#define SMSTRIDE_B 80
#define TILE_B     (128 * SMSTRIDE_B)    // 10240 per operand
#define STAGE_B    (4 * TILE_B)          // 40960
#define GNS        3
#define GEMM_SMEM  (GNS * STAGE_B)       // 122880

__device__ __forceinline__ uint32_t smem_u32(const void* p) {
    uint32_t a;
    asm("{ .reg .u64 t; cvta.to.shared.u64 t, %1; cvt.u32.u64 %0, t; }" : "=r"(a) : "l"(p));
    return a;
}

__device__ __forceinline__ void mma16816(float* c, const uint32_t* a, const uint32_t* b)
{
    asm volatile(
        "mma.sync.aligned.m16n8k16.row.col.f32.bf16.bf16.f32 "
        "{%0,%1,%2,%3}, {%4,%5,%6,%7}, {%8,%9}, {%0,%1,%2,%3};"
        : "+f"(c[0]), "+f"(c[1]), "+f"(c[2]), "+f"(c[3])
        : "r"(a[0]), "r"(a[1]), "r"(a[2]), "r"(a[3]), "r"(b[0]), "r"(b[1]));
}

#define LDSM_X4(r0, r1, r2, r3, addr) \
    asm volatile("ldmatrix.sync.aligned.m8n8.x4.shared.b16 {%0,%1,%2,%3}, [%4];" \
                 : "=r"(r0), "=r"(r1), "=r"(r2), "=r"(r3) : "r"(addr))

__global__ __launch_bounds__(256)
void gemm_mma(const __nv_bfloat16* __restrict__ Ahi, const __nv_bfloat16* __restrict__ Alo,
              const __nv_bfloat16* __restrict__ Bhi, const __nv_bfloat16* __restrict__ Blo,
              const float* __restrict__ bias, float* __restrict__ C,
              int M, int NT, int K)
{
    extern __shared__ char smem[];
    const uint32_t sb = smem_u32(smem);
    const int tid  = threadIdx.x;
    const int wid  = tid >> 5, lane = tid & 31;
    const int row0 = blockIdx.y * 128;
    const int col0 = blockIdx.x * 128;
    const int KT   = K >> 5;

    // ---- loader mapping: 4 operands x 64 threads; 128 rows x 4 x 16B chunks ----
    const int op     = tid >> 6;
    const int t64    = tid & 63;
    const int lchunk = t64 & 3;
    const int lrow0  = t64 >> 2;
    const __nv_bfloat16* lbase = (op == 0) ? Ahi : (op == 1) ? Alo : (op == 2) ? Bhi : Blo;
    const int  lr0 = (op < 2) ? row0 : col0;
    const bool isA = (op < 2);

    auto load_stage = [&](int slot, int kt) {
        uint32_t sdst0 = sb + slot * STAGE_B + op * TILE_B + lchunk * 16;
        const char* gsrc0 = (const char*)lbase + (size_t)kt * 64 + lchunk * 16;
#pragma unroll
        for (int rr = 0; rr < 8; rr++) {
            int r    = lrow0 + rr * 16;
            int grow = lr0 + r;
            int sz   = 16;
            if (isA && grow >= M) { grow = M - 1; sz = 0; }
            const char* src = gsrc0 + (size_t)grow * ((size_t)K * 2);
            uint32_t dst = sdst0 + (uint32_t)r * SMSTRIDE_B;
            asm volatile("cp.async.cg.shared.global [%0], [%1], 16, %2;"
                         :: "r"(dst), "l"(src), "r"(sz));
        }
    };

    // ---- compute mapping ----
    const int wm = wid & 3;               // 4 m-groups of 32 rows
    const int wn = wid >> 2;              // 2 n-groups of 64 cols
    const int g  = lane >> 2;
    const int t  = lane & 3;
    const int lane7 = lane & 7;
    const int quad  = lane >> 3;          // 0..3

    // ldmatrix per-lane row/byte offsets
    // A x4: m0=rows+0 k0-7, m1=rows+8 k0-7, m2=rows+0 k8-15, m3=rows+8 k8-15
    const int a_moff = (quad & 1) * 8;
    const int a_koff = (quad >> 1) * 16;
    // B x4: m0=(j,k0-7), m1=(j,k8-15), m2=(j+1,k0-7), m3=(j+1,k8-15)
    const int b_noff = (quad >> 1) * 8;
    const int b_koff = (quad & 1) * 16;

    float acc[2][8][4];
#pragma unroll
    for (int i = 0; i < 2; i++)
#pragma unroll
        for (int j = 0; j < 8; j++)
#pragma unroll
            for (int r = 0; r < 4; r++) acc[i][j][r] = 0.f;

    // prologue: stages 0,1
    load_stage(0, 0);
    asm volatile("cp.async.commit_group;" ::: "memory");
    load_stage(1, 1);
    asm volatile("cp.async.commit_group;" ::: "memory");

    int slot = 0;
    for (int kt = 0; kt < KT; kt++) {
        __syncthreads();                       // all warps done computing slot (kt-1)%3
        if (kt + 2 < KT) load_stage((kt + 2) % GNS, kt + 2);
        asm volatile("cp.async.commit_group;" ::: "memory");
        asm volatile("cp.async.wait_group %0;" :: "n"(GNS - 1) : "memory");
        __syncthreads();                       // stage kt visible to all warps

        const uint32_t sAh = sb + slot * STAGE_B;
        const uint32_t sAl = sAh + TILE_B;
        const uint32_t sBh = sAh + 2 * TILE_B;
        const uint32_t sBl = sAh + 3 * TILE_B;

#pragma unroll
        for (int kh = 0; kh < 2; kh++) {
            const int kb = kh * 32;

            uint32_t ah[2][4], al[2][4];
#pragma unroll
            for (int i = 0; i < 2; i++) {
                uint32_t ra = (uint32_t)(wm * 32 + i * 16 + a_moff + lane7) * SMSTRIDE_B
                              + kb + a_koff;
                LDSM_X4(ah[i][0], ah[i][1], ah[i][2], ah[i][3], sAh + ra);
                LDSM_X4(al[i][0], al[i][1], al[i][2], al[i][3], sAl + ra);
            }
#pragma unroll
            for (int jp = 0; jp < 4; jp++) {
                uint32_t rb = (uint32_t)(wn * 64 + jp * 16 + b_noff + lane7) * SMSTRIDE_B
                              + kb + b_koff;
                uint32_t bh[4], bl[4];
                LDSM_X4(bh[0], bh[1], bh[2], bh[3], sBh + rb);
                LDSM_X4(bl[0], bl[1], bl[2], bl[3], sBl + rb);
#pragma unroll
                for (int jj = 0; jj < 2; jj++) {
                    int j = jp * 2 + jj;
#pragma unroll
                    for (int i = 0; i < 2; i++) {
                        mma16816(acc[i][j], ah[i], &bh[jj * 2]);
                        mma16816(acc[i][j], ah[i], &bl[jj * 2]);
                        mma16816(acc[i][j], al[i], &bh[jj * 2]);
                    }
                }
            }
        }
        slot = (slot + 1 == GNS) ? 0 : slot + 1;
    }

    // ---- epilogue: bias + store ----
#pragma unroll
    for (int i = 0; i < 2; i++) {
        int gr0 = row0 + wm * 32 + i * 16 + g;
#pragma unroll
        for (int j = 0; j < 8; j++) {
            int gc = col0 + wn * 64 + j * 8 + t * 2;
            float b0 = bias[gc], b1 = bias[gc + 1];
            if (gr0 < M) {
                float2 o = make_float2(acc[i][j][0] + b0, acc[i][j][1] + b1);
                *(float2*)&C[(size_t)gr0 * NT + gc] = o;
            }
            if (gr0 + 8 < M) {
                float2 o = make_float2(acc[i][j][2] + b0, acc[i][j][3] + b1);
                *(float2*)&C[(size_t)(gr0 + 8) * NT + gc] = o;
            }
        }
    }
}

// ===================== conversion / prologue kernels =====================
__global__ __launch_bounds__(256)
void split_x(const float* __restrict__ x)
{
    int i = blockIdx.x * blockDim.x + threadIdx.x;
    if (i < NN * IN_DIM) {
        float v = x[i];
        __nv_bfloat16 h = __float2bfloat16(v);
        g_xhi[i] = h;
        g_xlo[i] = __float2bfloat16(v - __bfloat162float(h));
    }
}

// ELU on packed h (g_b1 offset OFF_H) -> split bf16 contiguous [NN, D1]
__global__ __launch_bounds__(256)
void elu_split()
{
    int i = blockIdx.x * blockDim.x + threadIdx.x;
    if (i < NN * D1) {
        int node = i >> 11, c = i & 2047;
        float v = g_b1[(size_t)node * S1 + OFF_H + c];
        v = (v > 0.f) ? v : expm1f(v);
        __nv_bfloat16 h = __float2bfloat16(v);
        g_hhi[i] = h;
        g_hlo[i] = __float2bfloat16(v - __bfloat162float(h));
    }
}

// W[K,N] (n-contig) -> BT[Npad,K] K-major, split hi/lo. grid (K/32, Npad/32)
__global__ __launch_bounds__(256)
void transpose_split(const float* __restrict__ W, __nv_bfloat16* __restrict__ bthi,
                     __nv_bfloat16* __restrict__ btlo, int K, int N)
{
    __shared__ float tbuf[32][33];
    int k0 = blockIdx.x * 32, n0 = blockIdx.y * 32;
    int tx = threadIdx.x, ty = threadIdx.y;
#pragma unroll
    for (int i = ty; i < 32; i += 8) {
        int n = n0 + tx;
        tbuf[i][tx] = (n < N) ? W[(size_t)(k0 + i) * N + n] : 0.f;
    }
    __syncthreads();
#pragma unroll
    for (int i = ty; i < 32; i += 8) {
        float v = tbuf[tx][i];
        __nv_bfloat16 h = __float2bfloat16(v);
        size_t o = (size_t)(n0 + i) * K + (k0 + tx);
        bthi[o] = h;
        btlo[o] = __float2bfloat16(v - __bfloat162float(h));
    }
}

// pack bias segments: L1 [bq|bk|bv|bskip], L2 [bl|0pad|br|0pad]
__global__ __launch_bounds__(256)
void pack_bias(const float* __restrict__ bq, const float* __restrict__ bk,
               const float* __restrict__ bv, const float* __restrict__ bs,
               const float* __restrict__ bl, const float* __restrict__ br)
{
    int i = blockIdx.x * blockDim.x + threadIdx.x;
    if (i < N1TOT) {
        int seg = i >> 11, c = i & 2047;
        g_bias1[i] = (seg == 0) ? bq[c] : (seg == 1) ? bk[c] : (seg == 2) ? bv[c] : bs[c];
    }
    if (i < N2TOT) {
        int seg = i / D2PAD, c = i % D2PAD;
        g_bias2[i] = (c < D2) ? ((seg == 0) ? bl[c] : br[c]) : 0.f;
    }
}

// ===================== graph kernels =====================
__global__ __launch_bounds__(256)
void cvt_edges(const void* __restrict__ ei_raw)
{
    const long long* e64 = (const long long*)ei_raw;
    const int*       e32 = (const int*)ei_raw;
    bool is64 = true;
#pragma unroll
    for (int j = 0; j < 16; j++) {
        long long v = e64[j * 1000];
        if (v < 0 || v >= NN) { is64 = false; break; }
    }
    int e = blockIdx.x * blockDim.x + threadIdx.x;
    if (e >= EE) return;
    long long s, d;
    if (is64) { s = e64[2 * e]; d = e64[2 * e + 1]; }
    else      { s = e32[2 * e]; d = e32[2 * e + 1]; }
    if (s < 0) s = 0; if (s >= NN) s = NN - 1;
    if (d < 0) d = 0; if (d >= NN) d = NN - 1;
    g_src[e] = (int)s;
    g_dst[e] = (int)d;
}

__global__ void zero_denoms()
{
    int i = blockIdx.x * blockDim.x + threadIdx.x;
    if (i < NN * H1) g_den1[i] = 0.f;
    if (i < NN * H2) g_den2[i] = 0.f;
}

__global__ __launch_bounds__(128)
void attn1()
{
    int e = blockIdx.x;
    int h = threadIdx.x >> 5;
    int lane = threadIdx.x & 31;
    int s = g_src[e], d = g_dst[e];
    const float4* qp = (const float4*)&g_b1[(size_t)d * S1 + OFF_Q + h * C1];
    const float4* kp = (const float4*)&g_b1[(size_t)s * S1 + OFF_K + h * C1];
    float acc = 0.f;
#pragma unroll 4
    for (int i = lane; i < C1 / 4; i += 32) {
        float4 a = qp[i], b = kp[i];
        acc += a.x * b.x + a.y * b.y + a.z * b.z + a.w * b.w;
    }
#pragma unroll
    for (int o = 16; o; o >>= 1) acc += __shfl_xor_sync(0xFFFFFFFFu, acc, o);
    if (lane == 0) {
        float ex = expf(acc * 0.04419417382415922f);
        g_ex1[e * H1 + h] = ex;
        atomicAdd(&g_den1[d * H1 + h], ex);
    }
}

__global__ __launch_bounds__(256)
void agg1()
{
    int e = blockIdx.x;
    int s = g_src[e], d = g_dst[e];
    for (int c = threadIdx.x * 4; c < D1; c += 256 * 4) {
        int h = c >> 9;
        float w = g_ex1[e * H1 + h] / (g_den1[d * H1 + h] + 1e-16f);
        float4 vv = *(const float4*)&g_b1[(size_t)s * S1 + OFF_V + c];
        float* hp = &g_b1[(size_t)d * S1 + OFF_H + c];
        atomicAdd(hp + 0, vv.x * w);
        atomicAdd(hp + 1, vv.y * w);
        atomicAdd(hp + 2, vv.z * w);
        atomicAdd(hp + 3, vv.w * w);
    }
}

__global__ __launch_bounds__(256)
void attn2(const float* __restrict__ att)
{
    int e = blockIdx.x;
    int h = threadIdx.x >> 5;
    int lane = threadIdx.x & 31;
    int s, d;
    if (e < EE) { s = g_src[e]; d = g_dst[e]; }
    else        { s = d = e - EE; }
    const float* glp = &g_b2[(size_t)s * S2 + h * C2];
    const float* grp = &g_b2[(size_t)d * S2 + D2PAD + h * C2];
    const float* ap  = &att[h * C2];
    float acc = 0.f;
    for (int i = lane; i < C2; i += 32) {
        float x = glp[i] + grp[i];
        x = (x > 0.f) ? x : 0.2f * x;
        acc += x * ap[i];
    }
#pragma unroll
    for (int o = 16; o; o >>= 1) acc += __shfl_xor_sync(0xFFFFFFFFu, acc, o);
    if (lane == 0) {
        float ex = expf(acc);
        g_ex2[e * H2 + h] = ex;
        atomicAdd(&g_den2[d * H2 + h], ex);
    }
}

__global__ void out_init(float* __restrict__ out, const float* __restrict__ b_out)
{
    int i = blockIdx.x * blockDim.x + threadIdx.x;
    if (i < NN * C2) out[i] = b_out[i % C2];
}

__global__ __launch_bounds__(256)
void agg2(float* __restrict__ out)
{
    int e = blockIdx.x;
    int s, d;
    if (e < EE) { s = g_src[e]; d = g_dst[e]; }
    else        { s = d = e - EE; }
    __shared__ float w[H2];
    if (threadIdx.x < H2)
        w[threadIdx.x] = g_ex2[e * H2 + threadIdx.x] /
                         (g_den2[d * H2 + threadIdx.x] + 1e-16f) * (1.f / H2);
    __syncthreads();
    const float* glp = &g_b2[(size_t)s * S2];
    for (int c = threadIdx.x; c < C2; c += 256) {
        float acc = 0.f;
#pragma unroll
        for (int h = 0; h < H2; h++) acc += glp[h * C2 + c] * w[h];
        atomicAdd(&out[(size_t)d * C2 + c], acc);
    }
}

// ===================== host launcher =====================
extern "C" void kernel_launch(void* const* d_in, const int* in_sizes, int n_in,
                              void* d_out, int out_size)
{
    const float* x     = (const float*)d_in[0];
    const void*  ei    = d_in[1];
    const float* Wq    = (const float*)d_in[2];
    const float* bq    = (const float*)d_in[3];
    const float* Wk    = (const float*)d_in[4];
    const float* bk    = (const float*)d_in[5];
    const float* Wv    = (const float*)d_in[6];
    const float* bv    = (const float*)d_in[7];
    const float* Wskip = (const float*)d_in[8];
    const float* bskip = (const float*)d_in[9];
    const float* Wl    = (const float*)d_in[10];
    const float* bl    = (const float*)d_in[11];
    const float* Wr    = (const float*)d_in[12];
    const float* br    = (const float*)d_in[13];
    const float* att   = (const float*)d_in[14];
    const float* b_out = (const float*)d_in[15];
    float*       out   = (float*)d_out;

    float *pb1, *pb2, *pbias1, *pbias2;
    cudaGetSymbolAddress((void**)&pb1,    g_b1);
    cudaGetSymbolAddress((void**)&pb2,    g_b2);
    cudaGetSymbolAddress((void**)&pbias1, g_bias1);
    cudaGetSymbolAddress((void**)&pbias2, g_bias2);
    __nv_bfloat16 *pxhi, *pxlo, *phhi, *phlo, *pb1h, *pb1l, *pb2h, *pb2l;
    cudaGetSymbolAddress((void**)&pxhi, g_xhi);
    cudaGetSymbolAddress((void**)&pxlo, g_xlo);
    cudaGetSymbolAddress((void**)&phhi, g_hhi);
    cudaGetSymbolAddress((void**)&phlo, g_hlo);
    cudaGetSymbolAddress((void**)&pb1h, g_bt1hi);
    cudaGetSymbolAddress((void**)&pb1l, g_bt1lo);
    cudaGetSymbolAddress((void**)&pb2h, g_bt2hi);
    cudaGetSymbolAddress((void**)&pb2l, g_bt2lo);

    cudaFuncSetAttribute(gemm_mma, cudaFuncAttributeMaxDynamicSharedMemorySize, GEMM_SMEM);

    // edge ingestion + state reset
    cvt_edges<<<(EE + 255) / 256, 256>>>(ei);
    zero_denoms<<<(NN * H2 + 255) / 256, 256>>>();
    pack_bias<<<(N1TOT + 255) / 256, 256>>>(bq, bk, bv, bskip, bl, br);

    // operand conversions
    split_x<<<(NN * IN_DIM + 255) / 256, 256>>>(x);
    {
        dim3 blk(32, 8);
        dim3 t1(IN_DIM / 32, D1 / 32);
        size_t w1 = (size_t)D1 * IN_DIM;
        transpose_split<<<t1, blk>>>(Wq,    pb1h + 0 * w1, pb1l + 0 * w1, IN_DIM, D1);
        transpose_split<<<t1, blk>>>(Wk,    pb1h + 1 * w1, pb1l + 1 * w1, IN_DIM, D1);
        transpose_split<<<t1, blk>>>(Wv,    pb1h + 2 * w1, pb1l + 2 * w1, IN_DIM, D1);
        transpose_split<<<t1, blk>>>(Wskip, pb1h + 3 * w1, pb1l + 3 * w1, IN_DIM, D1);
        dim3 t2(D1 / 32, D2PAD / 32);
        size_t w2 = (size_t)D2PAD * D1;
        transpose_split<<<t2, blk>>>(Wl, pb2h + 0 * w2, pb2l + 0 * w2, D1, D2);
        transpose_split<<<t2, blk>>>(Wr, pb2h + 1 * w2, pb2l + 1 * w2, D1, D2);
    }

    // --- layer 1 fused GEMM: [10000,1024] x [8192,1024]^T -> packed q|k|v|h ---
    {
        dim3 g1(N1TOT / 128, (NN + 127) / 128);   // (64, 79)
        gemm_mma<<<g1, 256, GEMM_SMEM>>>(pxhi, pxlo, pb1h, pb1l, pbias1, pb1,
                                         NN, N1TOT, IN_DIM);
    }

    // --- layer 1 attention + aggregation ---
    attn1<<<EE, 128>>>();
    agg1 <<<EE, 256>>>();
    elu_split<<<(NN * D1 + 255) / 256, 256>>>();

    // --- layer 2 fused GEMM: [10000,2048] x [7424,2048]^T -> packed gl|gr ---
    {
        dim3 g2(N2TOT / 128, (NN + 127) / 128);   // (58, 79)
        gemm_mma<<<g2, 256, GEMM_SMEM>>>(phhi, phlo, pb2h, pb2l, pbias2, pb2,
                                         NN, N2TOT, D1);
    }

    // --- layer 2 attention + output ---
    attn2<<<E2TOT, 256>>>(att);
    out_init<<<(NN * C2 + 255) / 256, 256>>>(out, b_out);
    agg2<<<E2TOT, 256>>>(out);
}